// round 3
// baseline (speedup 1.0000x reference)
#include <cuda_runtime.h>

// Inputs (metadata order):
//   d_in[0] t_inters : float32 [B, N, 2]   (B=4096, N=128)
//   d_in[1] weights  : float32 [B, N]
//   d_in[2] t_near   : float32 [B, 1]
//   d_in[3] t_far    : float32 [B, 1]
// Output: float32 [B]
//
// Sorted-u distortion identity:
//   loss = 2*sum_i w_i*(u_i*W_{<i} - S_{<i}) + (1/3)*sum_i w_i^2*ds_i
// Layout: one CTA (128 threads) per row, one element per thread.
// Block-wide exclusive scan of (w, w*u) via warp shuffles + tiny smem combine.

__global__ __launch_bounds__(128, 16)
void distor_value_kernel(const float2* __restrict__ t_inters,
                         const float*  __restrict__ weights,
                         const float*  __restrict__ t_near,
                         const float*  __restrict__ t_far,
                         float* __restrict__ out) {
    const int row  = blockIdx.x;
    const int tid  = threadIdx.x;          // element index within row (0..127)
    const int lane = tid & 31;
    const int wid  = tid >> 5;              // warp within row (0..3)

    __shared__ float sW[4], sS[4], sL[4];

    // Coalesced loads: 8B/thread from t_inters, 4B/thread from weights.
    const float2 tv = t_inters[(size_t)row * 128 + tid];
    const float  w  = weights [(size_t)row * 128 + tid];
    const float nearv = t_near[row];                 // broadcast load
    const float inv   = 1.0f / (t_far[row] - nearv); // broadcast load

    const float u  = ((tv.x + tv.y) * 0.5f - nearv) * inv;
    const float ds = (tv.y - tv.x) * inv;
    const float s  = w * u;

    // Warp-level inclusive scan of (w, s): 5 steps.
    float Wi = w, Si = s;
    #pragma unroll
    for (int off = 1; off < 32; off <<= 1) {
        float wUp = __shfl_up_sync(0xFFFFFFFFu, Wi, off);
        float sUp = __shfl_up_sync(0xFFFFFFFFu, Si, off);
        if (lane >= off) { Wi += wUp; Si += sUp; }
    }

    // Publish warp totals, combine across the 4 warps.
    if (lane == 31) { sW[wid] = Wi; sS[wid] = Si; }
    __syncthreads();
    float Woff = 0.0f, Soff = 0.0f;
    #pragma unroll
    for (int k = 0; k < 3; k++) {
        if (k < wid) { Woff += sW[k]; Soff += sS[k]; }
    }

    const float Wex = (Wi - w) + Woff;   // exclusive prefix of w
    const float Sex = (Si - s) + Soff;   // exclusive prefix of w*u

    // Per-element contribution.
    float loss = fmaf(2.0f * w, fmaf(u, Wex, -Sex),
                      w * w * ds * (1.0f / 3.0f));

    // Warp butterfly reduction, then cross-warp smem reduction.
    #pragma unroll
    for (int off = 16; off > 0; off >>= 1)
        loss += __shfl_xor_sync(0xFFFFFFFFu, loss, off);

    if (lane == 0) sL[wid] = loss;
    __syncthreads();
    if (tid == 0) out[row] = (sL[0] + sL[1]) + (sL[2] + sL[3]);
}

extern "C" void kernel_launch(void* const* d_in, const int* in_sizes, int n_in,
                              void* d_out, int out_size) {
    const float2* t_inters = (const float2*)d_in[0];
    const float*  weights  = (const float*)d_in[1];
    const float*  t_near   = (const float*)d_in[2];
    const float*  t_far    = (const float*)d_in[3];
    float* out = (float*)d_out;

    const int B = out_size;   // 4096 rows
    distor_value_kernel<<<B, 128>>>(t_inters, weights, t_near, t_far, out);
}

// round 4
// speedup vs baseline: 1.2605x; 1.2605x over previous
#include <cuda_runtime.h>

// Inputs (metadata order):
//   d_in[0] t_inters : float32 [B, N, 2]   (B=4096, N=128)
//   d_in[1] weights  : float32 [B, N]
//   d_in[2] t_near   : float32 [B, 1]
//   d_in[3] t_far    : float32 [B, 1]
// Output: float32 [B]
//
// Sorted-u distortion identity:
//   loss = 2*sum_i w_i*(u_i*W_{<i} - S_{<i}) + (1/3)*sum_i w_i^2*ds_i
//
// Layout: 4 rows per warp, processed as two split-lane pairs
// (lanes [0,16) -> even row, lanes [16,32) -> odd row of the pair).
// ALL global loads for all 4 rows are issued up front (high MLP) so the
// warp tolerates one full DRAM/L2 round-trip instead of two.

__device__ __forceinline__
float row_loss(float4 a0, float4 a1, float4 a2, float4 a3,
               float4 w0, float4 w1,
               float nearv, float farv, int sub) {
    const float inv = 1.0f / (farv - nearv);
    const float nh  = nearv * inv;

    float u[8], dsv[8], wv[8];
    u[0] = fmaf((a0.x + a0.y), 0.5f * inv, -nh);  dsv[0] = (a0.y - a0.x) * inv;
    u[1] = fmaf((a0.z + a0.w), 0.5f * inv, -nh);  dsv[1] = (a0.w - a0.z) * inv;
    u[2] = fmaf((a1.x + a1.y), 0.5f * inv, -nh);  dsv[2] = (a1.y - a1.x) * inv;
    u[3] = fmaf((a1.z + a1.w), 0.5f * inv, -nh);  dsv[3] = (a1.w - a1.z) * inv;
    u[4] = fmaf((a2.x + a2.y), 0.5f * inv, -nh);  dsv[4] = (a2.y - a2.x) * inv;
    u[5] = fmaf((a2.z + a2.w), 0.5f * inv, -nh);  dsv[5] = (a2.w - a2.z) * inv;
    u[6] = fmaf((a3.x + a3.y), 0.5f * inv, -nh);  dsv[6] = (a3.y - a3.x) * inv;
    u[7] = fmaf((a3.z + a3.w), 0.5f * inv, -nh);  dsv[7] = (a3.w - a3.z) * inv;
    wv[0] = w0.x; wv[1] = w0.y; wv[2] = w0.z; wv[3] = w0.w;
    wv[4] = w1.x; wv[5] = w1.y; wv[6] = w1.z; wv[7] = w1.w;

    float Wloc = 0.0f, Sloc = 0.0f;
    #pragma unroll
    for (int k = 0; k < 8; k++) { Wloc += wv[k]; Sloc = fmaf(wv[k], u[k], Sloc); }

    // Width-16 segmented inclusive scan (4 steps).
    float Winc = Wloc, Sinc = Sloc;
    #pragma unroll
    for (int off = 1; off < 16; off <<= 1) {
        float wUp = __shfl_up_sync(0xFFFFFFFFu, Winc, off, 16);
        float sUp = __shfl_up_sync(0xFFFFFFFFu, Sinc, off, 16);
        if (sub >= off) { Winc += wUp; Sinc += sUp; }
    }
    float Wr = Winc - Wloc;
    float Sr = Sinc - Sloc;

    float loss = 0.0f;
    #pragma unroll
    for (int k = 0; k < 8; k++) {
        loss = fmaf(2.0f * wv[k], fmaf(u[k], Wr, -Sr), loss);
        loss = fmaf(wv[k] * wv[k] * (1.0f / 3.0f), dsv[k], loss);
        Wr += wv[k];
        Sr  = fmaf(wv[k], u[k], Sr);
    }

    // Width-16 segmented butterfly reduction (4 steps).
    #pragma unroll
    for (int off = 8; off > 0; off >>= 1)
        loss += __shfl_xor_sync(0xFFFFFFFFu, loss, off, 16);
    return loss;
}

__global__ __launch_bounds__(256, 2)
void distor_value_kernel(const float4* __restrict__ ti4,
                         const float4* __restrict__ w4,
                         const float*  __restrict__ t_near,
                         const float*  __restrict__ t_far,
                         float* __restrict__ out,
                         int B) {
    const int warp = (int)((blockIdx.x * blockDim.x + threadIdx.x) >> 5);
    const int lane = (int)(threadIdx.x & 31);
    const int sub  = lane & 15;
    const int half = lane >> 4;

    const int row0 = warp * 4 + half;        // pair 0
    const int row1 = warp * 4 + 2 + half;    // pair 1
    if (warp * 4 >= B) return;               // B=4096 divisible by 4; rows valid

    // ---- Front-batched loads for all 4 rows (high MLP) ----
    const float4* tp0 = ti4 + (size_t)row0 * 64 + sub * 4;
    const float4* tp1 = ti4 + (size_t)row1 * 64 + sub * 4;
    const float4 a0 = tp0[0], a1 = tp0[1], a2 = tp0[2], a3 = tp0[3];
    const float4 b0 = tp1[0], b1 = tp1[1], b2 = tp1[2], b3 = tp1[3];
    const float4 wA = w4[(size_t)row0 * 32 + sub * 2 + 0];
    const float4 wB = w4[(size_t)row0 * 32 + sub * 2 + 1];
    const float4 wC = w4[(size_t)row1 * 32 + sub * 2 + 0];
    const float4 wD = w4[(size_t)row1 * 32 + sub * 2 + 1];
    const float n0 = t_near[row0], f0 = t_far[row0];
    const float n1 = t_near[row1], f1 = t_far[row1];

    const float l0 = row_loss(a0, a1, a2, a3, wA, wB, n0, f0, sub);
    const float l1 = row_loss(b0, b1, b2, b3, wC, wD, n1, f1, sub);

    if (sub == 0) {
        out[row0] = l0;
        out[row1] = l1;
    }
}

extern "C" void kernel_launch(void* const* d_in, const int* in_sizes, int n_in,
                              void* d_out, int out_size) {
    const float4* t_inters = (const float4*)d_in[0];
    const float4* weights  = (const float4*)d_in[1];
    const float*  t_near   = (const float*)d_in[2];
    const float*  t_far    = (const float*)d_in[3];
    float* out = (float*)d_out;

    const int B = out_size;                         // 4096 rows
    const int warps   = B / 4;                      // 1024 warps
    const int threads = 256;                        // 8 warps / CTA
    const int blocks  = (warps * 32) / threads;     // 128 CTAs
    distor_value_kernel<<<blocks, threads>>>(t_inters, weights, t_near, t_far, out, B);
}

// round 5
// speedup vs baseline: 1.3029x; 1.0337x over previous
#include <cuda_runtime.h>
#include <cstdint>

// Inputs (metadata order):
//   d_in[0] t_inters : float32 [B, N, 2]   (B=4096, N=128)
//   d_in[1] weights  : float32 [B, N]
//   d_in[2] t_near   : float32 [B, 1]
//   d_in[3] t_far    : float32 [B, 1]
// Output: float32 [B]
//
// Sorted-u distortion identity:
//   loss = 2*sum_i w_i*(u_i*W_{<i} - S_{<i}) + (1/3)*sum_i w_i^2*ds_i
//
// Strategy: bulk-async (TMA engine) copy of each CTA's entire slice into
// shared memory — bypasses the per-warp LDG outstanding-request cap that
// pinned all previous variants at ~1 TB/s. Compute then runs from smem:
// one warp per row, elements chunked 32-at-a-time (lane = element mod 32),
// so every LDS is consecutive and conflict-free.

__device__ __forceinline__ uint32_t smem_u32(const void* p) {
    return (uint32_t)__cvta_generic_to_shared(p);
}

__global__ __launch_bounds__(256, 4)
void distor_value_kernel(const float* __restrict__ ti,
                         const float* __restrict__ wgt,
                         const float* __restrict__ t_near,
                         const float* __restrict__ t_far,
                         float* __restrict__ out) {
    constexpr int ROWS = 8;                  // rows per CTA (one per warp)
    __shared__ __align__(16) float s_ti[ROWS * 256];   // 8 KB
    __shared__ __align__(16) float s_w [ROWS * 128];   // 4 KB
    __shared__ __align__(16) float s_near[ROWS];
    __shared__ __align__(16) float s_far [ROWS];
    __shared__ __align__(8)  unsigned long long s_mbar;

    const int tid  = threadIdx.x;
    const int lane = tid & 31;
    const int wid  = tid >> 5;               // warp id = row within CTA
    const int row0 = blockIdx.x * ROWS;

    const uint32_t mbar = smem_u32(&s_mbar);
    if (tid == 0) {
        asm volatile("mbarrier.init.shared.b64 [%0], %1;"
                     :: "r"(mbar), "r"(1) : "memory");
    }
    __syncthreads();

    if (tid == 0) {
        constexpr uint32_t TX = ROWS * 256 * 4 + ROWS * 128 * 4 + ROWS * 4 + ROWS * 4; // 12352
        asm volatile("mbarrier.arrive.expect_tx.shared.b64 _, [%0], %1;"
                     :: "r"(mbar), "r"(TX) : "memory");
        asm volatile("cp.async.bulk.shared::cluster.global.mbarrier::complete_tx::bytes [%0], [%1], %2, [%3];"
                     :: "r"(smem_u32(s_ti)), "l"(ti + (size_t)row0 * 256),
                        "r"((uint32_t)(ROWS * 256 * 4)), "r"(mbar) : "memory");
        asm volatile("cp.async.bulk.shared::cluster.global.mbarrier::complete_tx::bytes [%0], [%1], %2, [%3];"
                     :: "r"(smem_u32(s_w)), "l"(wgt + (size_t)row0 * 128),
                        "r"((uint32_t)(ROWS * 128 * 4)), "r"(mbar) : "memory");
        asm volatile("cp.async.bulk.shared::cluster.global.mbarrier::complete_tx::bytes [%0], [%1], %2, [%3];"
                     :: "r"(smem_u32(s_near)), "l"(t_near + row0),
                        "r"((uint32_t)(ROWS * 4)), "r"(mbar) : "memory");
        asm volatile("cp.async.bulk.shared::cluster.global.mbarrier::complete_tx::bytes [%0], [%1], %2, [%3];"
                     :: "r"(smem_u32(s_far)), "l"(t_far + row0),
                        "r"((uint32_t)(ROWS * 4)), "r"(mbar) : "memory");
    }

    // Wait (acquire) for all bulk copies: phase parity 0.
    asm volatile(
        "{\n\t"
        ".reg .pred P;\n"
        "WAIT_%=:\n\t"
        "mbarrier.try_wait.parity.acquire.cta.shared::cta.b64 P, [%0], %1;\n\t"
        "@!P bra WAIT_%=;\n\t"
        "}"
        :: "r"(mbar), "r"(0u) : "memory");

    // ---- Compute: warp `wid` handles row row0+wid, all from smem ----
    const float nv  = s_near[wid];
    const float inv = 1.0f / (s_far[wid] - nv);
    const float nh  = nv * inv;
    const float2* trow = reinterpret_cast<const float2*>(s_ti + wid * 256);
    const float*  wrow = s_w + wid * 128;

    float loss = 0.0f, Wbase = 0.0f, Sbase = 0.0f;
    #pragma unroll
    for (int c = 0; c < 4; c++) {
        const int e = c * 32 + lane;           // element index (lane-consecutive => conflict-free LDS)
        const float2 tv = trow[e];
        const float  w  = wrow[e];
        const float  u  = fmaf(tv.x + tv.y, 0.5f * inv, -nh);
        const float  ds = (tv.y - tv.x) * inv;
        const float  s  = w * u;

        // Warp inclusive scan of (w, w*u) over this 32-element chunk.
        float Wi = w, Si = s;
        #pragma unroll
        for (int off = 1; off < 32; off <<= 1) {
            float wUp = __shfl_up_sync(0xFFFFFFFFu, Wi, off);
            float sUp = __shfl_up_sync(0xFFFFFFFFu, Si, off);
            if (lane >= off) { Wi += wUp; Si += sUp; }
        }
        const float Wex = Wbase + (Wi - w);    // exclusive prefix over full row
        const float Sex = Sbase + (Si - s);

        loss = fmaf(2.0f * w, fmaf(u, Wex, -Sex), loss);
        loss = fmaf(w * w * (1.0f / 3.0f), ds, loss);

        // Carry chunk totals forward.
        Wbase += __shfl_sync(0xFFFFFFFFu, Wi, 31);
        Sbase += __shfl_sync(0xFFFFFFFFu, Si, 31);
    }

    // Warp butterfly reduction of per-lane loss.
    #pragma unroll
    for (int off = 16; off > 0; off >>= 1)
        loss += __shfl_xor_sync(0xFFFFFFFFu, loss, off);

    if (lane == 0) out[row0 + wid] = loss;
}

extern "C" void kernel_launch(void* const* d_in, const int* in_sizes, int n_in,
                              void* d_out, int out_size) {
    const float* t_inters = (const float*)d_in[0];
    const float* weights  = (const float*)d_in[1];
    const float* t_near   = (const float*)d_in[2];
    const float* t_far    = (const float*)d_in[3];
    float* out = (float*)d_out;

    const int B = out_size;            // 4096 rows
    const int blocks = B / 8;          // 512 CTAs, 8 rows each
    distor_value_kernel<<<blocks, 256>>>(t_inters, weights, t_near, t_far, out);
}

// round 6
// speedup vs baseline: 1.3092x; 1.0048x over previous
#include <cuda_runtime.h>

// Inputs (metadata order):
//   d_in[0] t_inters : float32 [B, N, 2]   (B=4096, N=128)
//   d_in[1] weights  : float32 [B, N]
//   d_in[2] t_near   : float32 [B, 1]
//   d_in[3] t_far    : float32 [B, 1]
// Output: float32 [B]
//
// Single-scan sorted-u identity:
//   inter = 2*sum_i w_i u_i (2*W_{<i} + w_i)  -  2*W_tot * sum_i w_i u_i
//   intra = (1/3) * sum_i w_i^2 * ds_i
// Only w needs a prefix scan; epilogue is 3 independent butterflies.
//
// Layout (best-measured config): 2 rows per warp, lanes [0,16) -> row0,
// lanes [16,32) -> row1, 8 elements per lane, 256 CTAs x 256 threads.

__global__ __launch_bounds__(256, 4)
void distor_value_kernel(const float* __restrict__ t_inters,
                         const float* __restrict__ weights,
                         const float* __restrict__ t_near,
                         const float* __restrict__ t_far,
                         float* __restrict__ out,
                         int B) {
    const int warp = (int)((blockIdx.x * blockDim.x + threadIdx.x) >> 5);
    const int lane = (int)(threadIdx.x & 31);
    const int sub  = lane & 15;
    int row        = warp * 2 + (lane >> 4);
    if (warp * 2 >= B) return;
    const bool valid = (row < B);
    if (!valid) row = B - 1;

    // ---- Front-batched loads (6x LDG.128 + 2 scalars) ----
    const float4* ti = reinterpret_cast<const float4*>(t_inters) + (size_t)row * 64 + sub * 4;
    const float4  a0 = ti[0];
    const float4  a1 = ti[1];
    const float4  a2 = ti[2];
    const float4  a3 = ti[3];
    const float4* wp = reinterpret_cast<const float4*>(weights) + (size_t)row * 32 + sub * 2;
    const float4  w0 = wp[0];
    const float4  w1 = wp[1];
    const float nearv = t_near[row];
    const float inv   = 1.0f / (t_far[row] - nearv);
    const float nh    = nearv * inv;

    float u[8], dsv[8], wv[8];
    u[0] = fmaf((a0.x + a0.y), 0.5f * inv, -nh);  dsv[0] = (a0.y - a0.x) * inv;
    u[1] = fmaf((a0.z + a0.w), 0.5f * inv, -nh);  dsv[1] = (a0.w - a0.z) * inv;
    u[2] = fmaf((a1.x + a1.y), 0.5f * inv, -nh);  dsv[2] = (a1.y - a1.x) * inv;
    u[3] = fmaf((a1.z + a1.w), 0.5f * inv, -nh);  dsv[3] = (a1.w - a1.z) * inv;
    u[4] = fmaf((a2.x + a2.y), 0.5f * inv, -nh);  dsv[4] = (a2.y - a2.x) * inv;
    u[5] = fmaf((a2.z + a2.w), 0.5f * inv, -nh);  dsv[5] = (a2.w - a2.z) * inv;
    u[6] = fmaf((a3.x + a3.y), 0.5f * inv, -nh);  dsv[6] = (a3.y - a3.x) * inv;
    u[7] = fmaf((a3.z + a3.w), 0.5f * inv, -nh);  dsv[7] = (a3.w - a3.z) * inv;
    wv[0] = w0.x; wv[1] = w0.y; wv[2] = w0.z; wv[3] = w0.w;
    wv[4] = w1.x; wv[5] = w1.y; wv[6] = w1.z; wv[7] = w1.w;

    // In-lane exclusive prefix of w (independent of the warp scan — starts now).
    float pw[8];
    pw[0] = 0.0f;
    #pragma unroll
    for (int k = 1; k < 8; k++) pw[k] = pw[k - 1] + wv[k - 1];
    const float Wloc = pw[7] + wv[7];

    // wu_k precomputed (also independent of the scan).
    float wu[8];
    #pragma unroll
    for (int k = 0; k < 8; k++) wu[k] = wv[k] * u[k];

    // Width-16 segmented inclusive scan of Wloc (4 steps) — the only scan.
    float Winc = Wloc;
    #pragma unroll
    for (int off = 1; off < 16; off <<= 1) {
        float wUp = __shfl_up_sync(0xFFFFFFFFu, Winc, off, 16);
        if (sub >= off) Winc += wUp;
    }
    const float Wr = Winc - Wloc;    // exclusive prefix of w at lane start

    // Three independent accumulators (tree-friendly, short chains).
    float A = 0.0f, Su = 0.0f, C = 0.0f;
    #pragma unroll
    for (int k = 0; k < 8; k++) {
        // A += w_k u_k * (2*(Wr + pw_k) + w_k)
        A  = fmaf(wu[k], fmaf(2.0f, Wr + pw[k], wv[k]), A);
        Su += wu[k];
        C  = fmaf(wv[k] * wv[k], dsv[k], C);
    }

    // Width-16 butterfly reduction of (A, Su, Wloc) — independent, pipelined.
    float Wt = Wloc;
    #pragma unroll
    for (int off = 8; off > 0; off >>= 1) {
        A  += __shfl_xor_sync(0xFFFFFFFFu, A,  off, 16);
        Su += __shfl_xor_sync(0xFFFFFFFFu, Su, off, 16);
        Wt += __shfl_xor_sync(0xFFFFFFFFu, Wt, off, 16);
    }

    if (valid && sub == 0)
        out[row] = 2.0f * fmaf(-Wt, Su, A) + C * (1.0f / 3.0f);
}

extern "C" void kernel_launch(void* const* d_in, const int* in_sizes, int n_in,
                              void* d_out, int out_size) {
    const float* t_inters = (const float*)d_in[0];
    const float* weights  = (const float*)d_in[1];
    const float* t_near   = (const float*)d_in[2];
    const float* t_far    = (const float*)d_in[3];
    float* out = (float*)d_out;

    const int B = out_size;                       // 4096 rows, 2 rows per warp
    const int warps   = (B + 1) / 2;              // 2048
    const int threads = 256;                      // 8 warps per CTA
    const int blocks  = (warps * 32 + threads - 1) / threads;  // 256
    distor_value_kernel<<<blocks, threads>>>(t_inters, weights, t_near, t_far, out, B);
}